// round 2
// baseline (speedup 1.0000x reference)
#include <cuda_runtime.h>
#include <math.h>

#define BATCH 2
#define EMB   512
#define SEQ   2048
#define NH    8
#define DHEAD 64
#define HWIN  64
#define N3E   1536   // 3*EMB

// Scratch buffers (allocation-free rule: __device__ globals)
__device__ float g_qkv[(size_t)BATCH * SEQ * N3E];   // [B*T, 3E]
__device__ float g_ctx[(size_t)BATCH * SEQ * EMB];   // [B*T, E]

// ---------------------------------------------------------------------------
// GEMM1: qkv[m,n] = sum_k x[b,k,t] * in_proj_w[n,k] + in_proj_b[n]
//   m = b*SEQ + t,  M=4096, N=1536, K=512
// ---------------------------------------------------------------------------
__global__ __launch_bounds__(256) void qkv_gemm_kernel(
    const float* __restrict__ x, const float* __restrict__ w,
    const float* __restrict__ bias)
{
    __shared__ float As[8][128];
    __shared__ float Bs[8][132];  // padded: conflict-free transposed store

    const int m0 = blockIdx.y * 128;
    const int n0 = blockIdx.x * 128;
    const int b  = m0 / SEQ;      // tiles never straddle batch (128 | 2048)
    const int t0 = m0 % SEQ;
    const float* Ab = x + (size_t)b * EMB * SEQ + t0;   // A(m,k)=Ab[k*SEQ+mi]

    const int tid = threadIdx.x;
    const int ty = tid >> 4, tx = tid & 15;

    float acc[8][8];
    #pragma unroll
    for (int i = 0; i < 8; i++)
        #pragma unroll
        for (int j = 0; j < 8; j++) acc[i][j] = 0.f;

    for (int k0 = 0; k0 < EMB; k0 += 8) {
        #pragma unroll
        for (int i = 0; i < 4; i++) {           // A tile: coalesced along t
            int idx = tid + i * 256;
            int k = idx >> 7, mi = idx & 127;
            As[k][mi] = Ab[(size_t)(k0 + k) * SEQ + mi];
        }
        #pragma unroll
        for (int i = 0; i < 4; i++) {           // B(k,n)=w[n*EMB+k]
            int idx = tid + i * 256;
            int k = idx & 7, ni = idx >> 3;
            Bs[k][ni] = w[(size_t)(n0 + ni) * EMB + k0 + k];
        }
        __syncthreads();

        #pragma unroll
        for (int kk = 0; kk < 8; kk++) {
            float4 a0 = *reinterpret_cast<const float4*>(&As[kk][ty * 8]);
            float4 a1 = *reinterpret_cast<const float4*>(&As[kk][ty * 8 + 4]);
            float4 b0 = *reinterpret_cast<const float4*>(&Bs[kk][tx * 8]);
            float4 b1 = *reinterpret_cast<const float4*>(&Bs[kk][tx * 8 + 4]);
            float av[8] = {a0.x,a0.y,a0.z,a0.w,a1.x,a1.y,a1.z,a1.w};
            float bv[8] = {b0.x,b0.y,b0.z,b0.w,b1.x,b1.y,b1.z,b1.w};
            #pragma unroll
            for (int i = 0; i < 8; i++)
                #pragma unroll
                for (int j = 0; j < 8; j++) acc[i][j] += av[i] * bv[j];
        }
        __syncthreads();
    }

    #pragma unroll
    for (int i = 0; i < 8; i++) {
        int m = m0 + ty * 8 + i;
        #pragma unroll
        for (int j = 0; j < 8; j++) {
            int n = n0 + tx * 8 + j;
            g_qkv[(size_t)m * N3E + n] = acc[i][j] + bias[n];
        }
    }
}

// ---------------------------------------------------------------------------
// Local-window attention. Grid: (SEQ/64, NH, BATCH). 256 threads (8 warps).
// Each block: 64 queries of one (b,h); key window = [q0-64, q0+127] (192 keys).
// Each warp: 8 queries; lane owns key slots {lane, lane+32, ..., lane+160}.
// ---------------------------------------------------------------------------
__global__ __launch_bounds__(256) void attn_kernel()
{
    extern __shared__ float sm[];
    float* Qs = sm;               // 64 * 64
    float* Ks = Qs + 64 * 64;     // 192 * 65 (padded: conflict-free col reads)
    float* Vs = Ks + 192 * 65;    // 192 * 64

    const int b  = blockIdx.z;
    const int h  = blockIdx.y;
    const int q0 = blockIdx.x * 64;
    const int tid = threadIdx.x;
    const float* base = g_qkv + (size_t)b * SEQ * N3E;
    const int qoff = h * DHEAD;
    const int koff = EMB + h * DHEAD;
    const int voff = 2 * EMB + h * DHEAD;

    for (int i = tid; i < 64 * 64; i += 256) {
        int qi = i >> 6, d = i & 63;
        Qs[qi * 64 + d] = base[(size_t)(q0 + qi) * N3E + qoff + d];
    }
    const int kstart = q0 - HWIN;
    for (int i = tid; i < 192 * 64; i += 256) {
        int ki = i >> 6, d = i & 63;
        int t = kstart + ki;
        float kv = 0.f, vv = 0.f;
        if (t >= 0 && t < SEQ) {
            kv = base[(size_t)t * N3E + koff + d];
            vv = base[(size_t)t * N3E + voff + d];
        }
        Ks[ki * 65 + d] = kv;
        Vs[ki * 64 + d] = vv;
    }
    __syncthreads();

    const int warp = tid >> 5, lane = tid & 31;
    const int qbase = warp * 8;
    const float scale = 0.125f;   // 1/sqrt(64)

    // ---- scores: s[u][kk] = Q[qbase+u] . K[lane+32*kk] ----
    float s[8][6];
    #pragma unroll
    for (int u = 0; u < 8; u++)
        #pragma unroll
        for (int kk = 0; kk < 6; kk++) s[u][kk] = 0.f;

    for (int d = 0; d < 64; d++) {
        float kv[6];
        #pragma unroll
        for (int kk = 0; kk < 6; kk++) kv[kk] = Ks[(lane + kk * 32) * 65 + d];
        #pragma unroll
        for (int u = 0; u < 8; u++) {
            float qv = Qs[(qbase + u) * 64 + d];
            #pragma unroll
            for (int kk = 0; kk < 6; kk++) s[u][kk] += qv * kv[kk];
        }
    }

    // ---- mask + softmax per query (probs stay in registers) ----
    #pragma unroll
    for (int u = 0; u < 8; u++) {
        int qi = qbase + u;               // local query idx; q = q0+qi
        float mx = -1e30f;
        #pragma unroll
        for (int kk = 0; kk < 6; kk++) {
            int ki = lane + kk * 32;
            int t = kstart + ki;
            // valid iff in-bounds and |q - t| <= 64  <=>  ki in [qi, qi+128]
            bool valid = (t >= 0) && (t < SEQ) && (ki >= qi) && (ki <= qi + 128);
            s[u][kk] = valid ? s[u][kk] * scale : -1e30f;
            mx = fmaxf(mx, s[u][kk]);
        }
        #pragma unroll
        for (int off = 16; off; off >>= 1)
            mx = fmaxf(mx, __shfl_xor_sync(0xffffffffu, mx, off));
        float sum = 0.f;
        #pragma unroll
        for (int kk = 0; kk < 6; kk++) { s[u][kk] = __expf(s[u][kk] - mx); sum += s[u][kk]; }
        #pragma unroll
        for (int off = 16; off; off >>= 1)
            sum += __shfl_xor_sync(0xffffffffu, sum, off);
        float inv = 1.f / sum;
        #pragma unroll
        for (int kk = 0; kk < 6; kk++) s[u][kk] *= inv;
    }

    // ---- PV: lane owns dims {2*lane, 2*lane+1}; probs via shuffle ----
    float a0[8], a1[8];
    #pragma unroll
    for (int u = 0; u < 8; u++) { a0[u] = 0.f; a1[u] = 0.f; }

    #pragma unroll
    for (int kk = 0; kk < 6; kk++) {
        #pragma unroll 8
        for (int src = 0; src < 32; src++) {
            int ki = kk * 32 + src;
            float2 v = *reinterpret_cast<const float2*>(&Vs[ki * 64 + 2 * lane]);
            #pragma unroll
            for (int u = 0; u < 8; u++) {
                float p = __shfl_sync(0xffffffffu, s[u][kk], src);
                a0[u] += p * v.x;
                a1[u] += p * v.y;
            }
        }
    }

    #pragma unroll
    for (int u = 0; u < 8; u++) {
        int q = q0 + qbase + u;
        float2* dst = reinterpret_cast<float2*>(
            g_ctx + ((size_t)(b * SEQ + q)) * EMB + qoff + 2 * lane);
        *dst = make_float2(a0[u], a1[u]);
    }
}

// ---------------------------------------------------------------------------
// GEMM2 + fused epilogue:
//   ao[m,n] = sum_k ctx[m,k]*out_w[n,k] + out_b[n]
//   out[b,n,t] = relu(ao * x[b,n,t])      (m = b*SEQ + t)
// M=4096, N=512, K=512
// ---------------------------------------------------------------------------
__global__ __launch_bounds__(256) void out_gemm_kernel(
    const float* __restrict__ x, const float* __restrict__ w,
    const float* __restrict__ bias, float* __restrict__ out)
{
    __shared__ float As[8][132];
    __shared__ float Bs[8][132];

    const int m0 = blockIdx.y * 128;
    const int n0 = blockIdx.x * 128;
    const int b  = m0 / SEQ;
    const int t0 = m0 % SEQ;
    const int tid = threadIdx.x;
    const int ty = tid >> 4, tx = tid & 15;

    float acc[8][8];
    #pragma unroll
    for (int i = 0; i < 8; i++)
        #pragma unroll
        for (int j = 0; j < 8; j++) acc[i][j] = 0.f;

    for (int k0 = 0; k0 < EMB; k0 += 8) {
        #pragma unroll
        for (int i = 0; i < 4; i++) {           // A(m,k)=ctx[m*EMB+k]
            int idx = tid + i * 256;
            int k = idx & 7, mi = idx >> 3;
            As[k][mi] = g_ctx[(size_t)(m0 + mi) * EMB + k0 + k];
        }
        #pragma unroll
        for (int i = 0; i < 4; i++) {           // B(k,n)=w[n*EMB+k]
            int idx = tid + i * 256;
            int k = idx & 7, ni = idx >> 3;
            Bs[k][ni] = w[(size_t)(n0 + ni) * EMB + k0 + k];
        }
        __syncthreads();

        #pragma unroll
        for (int kk = 0; kk < 8; kk++) {
            float4 a0 = *reinterpret_cast<const float4*>(&As[kk][ty * 8]);
            float4 a1 = *reinterpret_cast<const float4*>(&As[kk][ty * 8 + 4]);
            float4 b0 = *reinterpret_cast<const float4*>(&Bs[kk][tx * 8]);
            float4 b1 = *reinterpret_cast<const float4*>(&Bs[kk][tx * 8 + 4]);
            float av[8] = {a0.x,a0.y,a0.z,a0.w,a1.x,a1.y,a1.z,a1.w};
            float bv[8] = {b0.x,b0.y,b0.z,b0.w,b1.x,b1.y,b1.z,b1.w};
            #pragma unroll
            for (int i = 0; i < 8; i++)
                #pragma unroll
                for (int j = 0; j < 8; j++) acc[i][j] += av[i] * bv[j];
        }
        __syncthreads();
    }

    #pragma unroll
    for (int i = 0; i < 8; i++) {
        int t = t0 + ty * 8 + i;
        #pragma unroll
        for (int j = 0; j < 8; j++) {
            int n = n0 + tx * 8 + j;
            float v = acc[i][j] + bias[n];
            size_t idx = (size_t)b * EMB * SEQ + (size_t)n * SEQ + t;
            float r = v * x[idx];
            out[idx] = r > 0.f ? r : 0.f;
        }
    }
}

// ---------------------------------------------------------------------------
extern "C" void kernel_launch(void* const* d_in, const int* in_sizes, int n_in,
                              void* d_out, int out_size)
{
    const float* x  = (const float*)d_in[0];   // [B, E, T]
    const float* wi = (const float*)d_in[1];   // [3E, E]
    const float* bi = (const float*)d_in[2];   // [3E]
    const float* wo = (const float*)d_in[3];   // [E, E]
    const float* bo = (const float*)d_in[4];   // [E]
    float* out = (float*)d_out;                // [B, E, T]

    const int attn_smem = (64 * 64 + 192 * 65 + 192 * 64) * (int)sizeof(float);
    cudaFuncSetAttribute(attn_kernel,
                         cudaFuncAttributeMaxDynamicSharedMemorySize, attn_smem);

    qkv_gemm_kernel<<<dim3(N3E / 128, (BATCH * SEQ) / 128), 256>>>(x, wi, bi);
    attn_kernel<<<dim3(SEQ / 64, NH, BATCH), 256, attn_smem>>>();
    out_gemm_kernel<<<dim3(EMB / 128, (BATCH * SEQ) / 128), 256>>>(x, wo, bo, out);
}

// round 10
// speedup vs baseline: 1.2975x; 1.2975x over previous
#include <cuda_runtime.h>
#include <cuda_bf16.h>
#include <mma.h>
#include <stdint.h>
#include <math.h>

using namespace nvcuda;

#define BATCH 2
#define EMB   512
#define SEQ   2048
#define NH    8
#define DHEAD 64
#define HWIN  64
#define N3E   1536
#define MTOT  (BATCH * SEQ)     // 4096

// ---------------- scratch (allocation-free rule) ----------------
__device__ float g_qkv[(size_t)MTOT * N3E];   // [M, 3E]
__device__ float g_ctx[(size_t)MTOT * EMB];   // [M, E]

// ---------------- GEMM1 smem geometry ----------------
#define APAD 136    // A col-major: 32 k-rows x 128 t-cols (+8 pad), elements
#define BPAD 40     // B row-major: 128 n-rows x 32 k-cols (+8 pad), elements
#define A_TILE (32 * APAD)
#define B_TILE (128 * BPAD)

// ---------------------------------------------------------------------------
// GEMM1 (wmma bf16x3, preps fused in): qkv[m,n] = sum_k x^T[m,k]*W[n,k] + b[n]
// A is built col-major in smem straight from x[B,E,T] (no transpose kernel);
// fp32 -> bf16 hi/lo split happens in registers between LDG and STS.
// Per K-tile: acc += Ah*Bh + Ah*Bl + Al*Bh   (fp32 accumulators)
// ---------------------------------------------------------------------------
__global__ __launch_bounds__(256) void qkv_gemm_kernel(
    const float* __restrict__ x, const float* __restrict__ wgt,
    const float* __restrict__ bias)
{
    extern __shared__ __align__(128) __nv_bfloat16 smem[];
    __nv_bfloat16* Ah = smem;                 // [32][APAD]  (k, t) col-major A
    __nv_bfloat16* Al = Ah + A_TILE;
    __nv_bfloat16* Bh = Al + A_TILE;          // [128][BPAD] (n, k) row-major B
    __nv_bfloat16* Bl = Bh + B_TILE;

    const int tid  = threadIdx.x;
    const int wrp  = tid >> 5, lane = tid & 31;
    const int wm   = (wrp & 1) * 64;          // warp m-offset
    const int wn   = (wrp >> 1) * 32;         // warp n-offset
    const int m0   = blockIdx.y * 128;
    const int n0   = blockIdx.x * 128;
    const int b    = m0 / SEQ;
    const int t0   = m0 % SEQ;                // 128-row tiles never straddle batch
    const float* xb = x + (size_t)b * EMB * SEQ + t0;

    wmma::fragment<wmma::accumulator, 16, 16, 16, float> acc[4][2];
    #pragma unroll
    for (int mf = 0; mf < 4; mf++)
        #pragma unroll
        for (int nf = 0; nf < 2; nf++)
            wmma::fill_fragment(acc[mf][nf], 0.0f);

    for (int kc = 0; kc < EMB; kc += 32) {
        __syncthreads();    // previous iteration's fragment loads done

        // ---- A: x[b][kc+k][t0+tch*4 .. +3], k=idx>>5 (const per warp), coalesced
        #pragma unroll
        for (int rep = 0; rep < 4; rep++) {
            int idx = tid + rep * 256;
            int k = idx >> 5, tch = idx & 31;
            float4 v = *reinterpret_cast<const float4*>(xb + (size_t)(kc + k) * SEQ + tch * 4);
            __nv_bfloat162 h0, h1, l0, l1;
            h0.x = __float2bfloat16(v.x); h0.y = __float2bfloat16(v.y);
            h1.x = __float2bfloat16(v.z); h1.y = __float2bfloat16(v.w);
            l0.x = __float2bfloat16(v.x - __bfloat162float(h0.x));
            l0.y = __float2bfloat16(v.y - __bfloat162float(h0.y));
            l1.x = __float2bfloat16(v.z - __bfloat162float(h1.x));
            l1.y = __float2bfloat16(v.w - __bfloat162float(h1.y));
            int o = k * APAD + tch * 4;
            *reinterpret_cast<__nv_bfloat162*>(Ah + o)     = h0;
            *reinterpret_cast<__nv_bfloat162*>(Ah + o + 2) = h1;
            *reinterpret_cast<__nv_bfloat162*>(Al + o)     = l0;
            *reinterpret_cast<__nv_bfloat162*>(Al + o + 2) = l1;
        }
        // ---- B: wgt[(n0+n)*EMB + kc + kch*4 .. +3], row-contiguous, coalesced
        #pragma unroll
        for (int rep = 0; rep < 4; rep++) {
            int idx = tid + rep * 256;
            int n = idx >> 3, kch = idx & 7;
            float4 v = *reinterpret_cast<const float4*>(wgt + (size_t)(n0 + n) * EMB + kc + kch * 4);
            __nv_bfloat162 h0, h1, l0, l1;
            h0.x = __float2bfloat16(v.x); h0.y = __float2bfloat16(v.y);
            h1.x = __float2bfloat16(v.z); h1.y = __float2bfloat16(v.w);
            l0.x = __float2bfloat16(v.x - __bfloat162float(h0.x));
            l0.y = __float2bfloat16(v.y - __bfloat162float(h0.y));
            l1.x = __float2bfloat16(v.z - __bfloat162float(h1.x));
            l1.y = __float2bfloat16(v.w - __bfloat162float(h1.y));
            int o = n * BPAD + kch * 4;
            *reinterpret_cast<__nv_bfloat162*>(Bh + o)     = h0;
            *reinterpret_cast<__nv_bfloat162*>(Bh + o + 2) = h1;
            *reinterpret_cast<__nv_bfloat162*>(Bl + o)     = l0;
            *reinterpret_cast<__nv_bfloat162*>(Bl + o + 2) = l1;
        }
        __syncthreads();

        #pragma unroll
        for (int ks = 0; ks < 2; ks++) {      // two k=16 steps per K-tile=32
            wmma::fragment<wmma::matrix_a, 16, 16, 16, __nv_bfloat16, wmma::col_major> ah[4], al[4];
            wmma::fragment<wmma::matrix_b, 16, 16, 16, __nv_bfloat16, wmma::col_major> bh[2], bl[2];
            #pragma unroll
            for (int mf = 0; mf < 4; mf++) {
                const int o = ks * 16 * APAD + wm + mf * 16;   // (k=ks*16, m=wm+mf*16)
                wmma::load_matrix_sync(ah[mf], Ah + o, APAD);
                wmma::load_matrix_sync(al[mf], Al + o, APAD);
            }
            #pragma unroll
            for (int nf = 0; nf < 2; nf++) {
                const int o = (wn + nf * 16) * BPAD + ks * 16; // (k=ks*16, n=wn+nf*16)
                wmma::load_matrix_sync(bh[nf], Bh + o, BPAD);
                wmma::load_matrix_sync(bl[nf], Bl + o, BPAD);
            }
            #pragma unroll
            for (int mf = 0; mf < 4; mf++)
                #pragma unroll
                for (int nf = 0; nf < 2; nf++) {
                    wmma::mma_sync(acc[mf][nf], ah[mf], bh[nf], acc[mf][nf]);
                    wmma::mma_sync(acc[mf][nf], ah[mf], bl[nf], acc[mf][nf]);
                    wmma::mma_sync(acc[mf][nf], al[mf], bh[nf], acc[mf][nf]);
                }
        }
    }
    __syncthreads();   // all warps done with tiles before smem reuse

    // Epilogue: per-warp 16x16 fp32 patch in reused smem, add bias, write out.
    float* patch = reinterpret_cast<float*>(smem) + wrp * 256;
    const int pr = lane >> 1;
    const int pc = (lane & 1) * 8;
    #pragma unroll
    for (int mf = 0; mf < 4; mf++) {
        #pragma unroll
        for (int nf = 0; nf < 2; nf++) {
            wmma::store_matrix_sync(patch, acc[mf][nf], 16, wmma::mem_row_major);
            __syncwarp();
            const int gm = m0 + wm + mf * 16 + pr;
            const int gn = n0 + wn + nf * 16 + pc;
            float* dst = g_qkv + (size_t)gm * N3E + gn;
            #pragma unroll
            for (int j = 0; j < 8; j++)
                dst[j] = patch[pr * 16 + pc + j] + bias[gn + j];
            __syncwarp();
        }
    }
}

// ---------------- local-window attention (R2 known-good, fp32 ctx out) ----------------
__global__ __launch_bounds__(256) void attn_kernel()
{
    extern __shared__ float sm[];
    float* Qs = sm;               // 64 * 64
    float* Ks = Qs + 64 * 64;     // 192 * 65
    float* Vs = Ks + 192 * 65;    // 192 * 64

    const int b  = blockIdx.z;
    const int h  = blockIdx.y;
    const int q0 = blockIdx.x * 64;
    const int tid = threadIdx.x;
    const float* base = g_qkv + (size_t)b * SEQ * N3E;
    const int qoff = h * DHEAD;
    const int koff = EMB + h * DHEAD;
    const int voff = 2 * EMB + h * DHEAD;

    for (int i = tid; i < 64 * 64; i += 256) {
        int qi = i >> 6, d = i & 63;
        Qs[qi * 64 + d] = base[(size_t)(q0 + qi) * N3E + qoff + d];
    }
    const int kstart = q0 - HWIN;
    for (int i = tid; i < 192 * 64; i += 256) {
        int ki = i >> 6, d = i & 63;
        int t = kstart + ki;
        float kv = 0.f, vv = 0.f;
        if (t >= 0 && t < SEQ) {
            kv = base[(size_t)t * N3E + koff + d];
            vv = base[(size_t)t * N3E + voff + d];
        }
        Ks[ki * 65 + d] = kv;
        Vs[ki * 64 + d] = vv;
    }
    __syncthreads();

    const int warp = tid >> 5, lane = tid & 31;
    const int qbase = warp * 8;
    const float scale = 0.125f;

    float s[8][6];
    #pragma unroll
    for (int u = 0; u < 8; u++)
        #pragma unroll
        for (int kk = 0; kk < 6; kk++) s[u][kk] = 0.f;

    for (int d = 0; d < 64; d++) {
        float kv[6];
        #pragma unroll
        for (int kk = 0; kk < 6; kk++) kv[kk] = Ks[(lane + kk * 32) * 65 + d];
        #pragma unroll
        for (int u = 0; u < 8; u++) {
            float qv = Qs[(qbase + u) * 64 + d];
            #pragma unroll
            for (int kk = 0; kk < 6; kk++) s[u][kk] += qv * kv[kk];
        }
    }

    #pragma unroll
    for (int u = 0; u < 8; u++) {
        int qi = qbase + u;
        float mx = -1e30f;
        #pragma unroll
        for (int kk = 0; kk < 6; kk++) {
            int ki = lane + kk * 32;
            int t = kstart + ki;
            bool valid = (t >= 0) && (t < SEQ) && (ki >= qi) && (ki <= qi + 128);
            s[u][kk] = valid ? s[u][kk] * scale : -1e30f;
            mx = fmaxf(mx, s[u][kk]);
        }
        #pragma unroll
        for (int off = 16; off; off >>= 1)
            mx = fmaxf(mx, __shfl_xor_sync(0xffffffffu, mx, off));
        float sum = 0.f;
        #pragma unroll
        for (int kk = 0; kk < 6; kk++) { s[u][kk] = __expf(s[u][kk] - mx); sum += s[u][kk]; }
        #pragma unroll
        for (int off = 16; off; off >>= 1)
            sum += __shfl_xor_sync(0xffffffffu, sum, off);
        float inv = 1.f / sum;
        #pragma unroll
        for (int kk = 0; kk < 6; kk++) s[u][kk] *= inv;
    }

    float a0[8], a1[8];
    #pragma unroll
    for (int u = 0; u < 8; u++) { a0[u] = 0.f; a1[u] = 0.f; }

    #pragma unroll
    for (int kk = 0; kk < 6; kk++) {
        #pragma unroll 8
        for (int src = 0; src < 32; src++) {
            int ki = kk * 32 + src;
            float2 v = *reinterpret_cast<const float2*>(&Vs[ki * 64 + 2 * lane]);
            #pragma unroll
            for (int u = 0; u < 8; u++) {
                float p = __shfl_sync(0xffffffffu, s[u][kk], src);
                a0[u] += p * v.x;
                a1[u] += p * v.y;
            }
        }
    }

    #pragma unroll
    for (int u = 0; u < 8; u++) {
        int q = q0 + qbase + u;
        float2* dst = reinterpret_cast<float2*>(
            g_ctx + ((size_t)(b * SEQ + q)) * EMB + qoff + 2 * lane);
        *dst = make_float2(a0[u], a1[u]);
    }
}

// ---------------- GEMM2 (R2 known-good SIMT) ----------------
__global__ __launch_bounds__(256) void out_gemm_kernel(
    const float* __restrict__ x, const float* __restrict__ w,
    const float* __restrict__ bias, float* __restrict__ out)
{
    __shared__ float As[8][132];
    __shared__ float Bs[8][132];

    const int m0 = blockIdx.y * 128;
    const int n0 = blockIdx.x * 128;
    const int b  = m0 / SEQ;
    const int t0 = m0 % SEQ;
    const int tid = threadIdx.x;
    const int ty = tid >> 4, tx = tid & 15;

    float acc[8][8];
    #pragma unroll
    for (int i = 0; i < 8; i++)
        #pragma unroll
        for (int j = 0; j < 8; j++) acc[i][j] = 0.f;

    for (int k0 = 0; k0 < EMB; k0 += 8) {
        #pragma unroll
        for (int i = 0; i < 4; i++) {
            int idx = tid + i * 256;
            int k = idx & 7, mi = idx >> 3;
            As[k][mi] = g_ctx[(size_t)(m0 + mi) * EMB + k0 + k];
        }
        #pragma unroll
        for (int i = 0; i < 4; i++) {
            int idx = tid + i * 256;
            int k = idx & 7, ni = idx >> 3;
            Bs[k][ni] = w[(size_t)(n0 + ni) * EMB + k0 + k];
        }
        __syncthreads();

        #pragma unroll
        for (int kk = 0; kk < 8; kk++) {
            float4 a0 = *reinterpret_cast<const float4*>(&As[kk][ty * 8]);
            float4 a1 = *reinterpret_cast<const float4*>(&As[kk][ty * 8 + 4]);
            float4 b0 = *reinterpret_cast<const float4*>(&Bs[kk][tx * 8]);
            float4 b1 = *reinterpret_cast<const float4*>(&Bs[kk][tx * 8 + 4]);
            float av[8] = {a0.x,a0.y,a0.z,a0.w,a1.x,a1.y,a1.z,a1.w};
            float bv[8] = {b0.x,b0.y,b0.z,b0.w,b1.x,b1.y,b1.z,b1.w};
            #pragma unroll
            for (int i = 0; i < 8; i++)
                #pragma unroll
                for (int j = 0; j < 8; j++) acc[i][j] += av[i] * bv[j];
        }
        __syncthreads();
    }

    #pragma unroll
    for (int i = 0; i < 8; i++) {
        int t = t0 + ty * 8 + i;
        #pragma unroll
        for (int j = 0; j < 8; j++) {
            int n = n0 + tx * 8 + j;
            float v = acc[i][j] + bias[n];
            size_t idx = (size_t)b * EMB * SEQ + (size_t)n * SEQ + t;
            float r = v * x[idx];
            out[idx] = r > 0.f ? r : 0.f;
        }
    }
}

// ---------------------------------------------------------------------------
extern "C" void kernel_launch(void* const* d_in, const int* in_sizes, int n_in,
                              void* d_out, int out_size)
{
    const float* x  = (const float*)d_in[0];   // [B, E, T]
    const float* wi = (const float*)d_in[1];   // [3E, E]
    const float* bi = (const float*)d_in[2];   // [3E]
    const float* wo = (const float*)d_in[3];   // [E, E]
    const float* bo = (const float*)d_in[4];   // [E]
    float* out = (float*)d_out;                // [B, E, T]

    const int gemm1_smem = (2 * A_TILE + 2 * B_TILE) * (int)sizeof(__nv_bfloat16) + 128;
    const int attn_smem  = (64 * 64 + 192 * 65 + 192 * 64) * (int)sizeof(float);

    cudaFuncSetAttribute(qkv_gemm_kernel,
                         cudaFuncAttributeMaxDynamicSharedMemorySize, gemm1_smem);
    cudaFuncSetAttribute(attn_kernel,
                         cudaFuncAttributeMaxDynamicSharedMemorySize, attn_smem);

    qkv_gemm_kernel<<<dim3(N3E / 128, MTOT / 128), 256, gemm1_smem>>>(x, wi, bi);
    attn_kernel<<<dim3(SEQ / 64, NH, BATCH), 256, attn_smem>>>();
    out_gemm_kernel<<<dim3(EMB / 128, MTOT / 128), 256>>>(x, wo, bo, out);
}

// round 11
// speedup vs baseline: 1.6354x; 1.2605x over previous
#include <cuda_runtime.h>
#include <cuda_bf16.h>
#include <mma.h>
#include <stdint.h>
#include <math.h>

using namespace nvcuda;

#define BATCH 2
#define EMB   512
#define SEQ   2048
#define NH    8
#define DHEAD 64
#define HWIN  64
#define N3E   1536
#define MTOT  (BATCH * SEQ)     // 4096

// ---------------- scratch (allocation-free rule) ----------------
__device__ float g_qkv[(size_t)MTOT * N3E];   // [M, 3E]
__device__ float g_ctx[(size_t)MTOT * EMB];   // [M, E]

// ---------------- smem geometry ----------------
#define APAD 136    // GEMM1 A col-major: 32 k-rows x 128 t-cols (+8), elems
#define BPAD 40     // row-major operand: 128 rows x 32 k (+8), elems
#define A_TILE (32 * APAD)
#define B_TILE (128 * BPAD)

__device__ __forceinline__ void split4(const float4& v, __nv_bfloat162& h0,
                                       __nv_bfloat162& h1, __nv_bfloat162& l0,
                                       __nv_bfloat162& l1)
{
    h0.x = __float2bfloat16(v.x); h0.y = __float2bfloat16(v.y);
    h1.x = __float2bfloat16(v.z); h1.y = __float2bfloat16(v.w);
    l0.x = __float2bfloat16(v.x - __bfloat162float(h0.x));
    l0.y = __float2bfloat16(v.y - __bfloat162float(h0.y));
    l1.x = __float2bfloat16(v.z - __bfloat162float(h1.x));
    l1.y = __float2bfloat16(v.w - __bfloat162float(h1.y));
}

// ---------------------------------------------------------------------------
// GEMM1 (wmma bf16x3, fused split, register-double-buffered):
//   qkv[m,n] = sum_k x^T[m,k]*W[n,k] + bias[n]
// ---------------------------------------------------------------------------
__global__ __launch_bounds__(256) void qkv_gemm_kernel(
    const float* __restrict__ x, const float* __restrict__ wgt,
    const float* __restrict__ bias)
{
    extern __shared__ __align__(128) __nv_bfloat16 smem[];
    __nv_bfloat16* Ah = smem;                 // [32][APAD]  (k, t) col-major A
    __nv_bfloat16* Al = Ah + A_TILE;
    __nv_bfloat16* Bh = Al + A_TILE;          // [128][BPAD] (n, k) row-major B
    __nv_bfloat16* Bl = Bh + B_TILE;

    const int tid  = threadIdx.x;
    const int wrp  = tid >> 5, lane = tid & 31;
    const int wm   = (wrp & 1) * 64;
    const int wn   = (wrp >> 1) * 32;
    const int m0   = blockIdx.y * 128;
    const int n0   = blockIdx.x * 128;
    const int b    = m0 / SEQ;
    const int t0   = m0 % SEQ;
    const float* xb = x + (size_t)b * EMB * SEQ + t0;

    // per-thread load coordinates (fixed across iterations)
    const int ak  = tid >> 5;            // +8 per rep
    const int atc = tid & 31;
    const int bn  = tid >> 3;            // +32 per rep
    const int bkc = tid & 7;

    wmma::fragment<wmma::accumulator, 16, 16, 16, float> acc[4][2];
    #pragma unroll
    for (int mf = 0; mf < 4; mf++)
        #pragma unroll
        for (int nf = 0; nf < 2; nf++)
            wmma::fill_fragment(acc[mf][nf], 0.0f);

    float4 pa[4], pb[4];
    #pragma unroll
    for (int rep = 0; rep < 4; rep++) {
        pa[rep] = *reinterpret_cast<const float4*>(xb + (size_t)(ak + rep * 8) * SEQ + atc * 4);
        pb[rep] = *reinterpret_cast<const float4*>(wgt + (size_t)(n0 + bn + rep * 32) * EMB + bkc * 4);
    }

    for (int kc = 0; kc < EMB; kc += 32) {
        __syncthreads();    // previous iteration's fragment loads done
        #pragma unroll
        for (int rep = 0; rep < 4; rep++) {
            __nv_bfloat162 h0, h1, l0, l1;
            split4(pa[rep], h0, h1, l0, l1);
            int o = (ak + rep * 8) * APAD + atc * 4;
            *reinterpret_cast<__nv_bfloat162*>(Ah + o)     = h0;
            *reinterpret_cast<__nv_bfloat162*>(Ah + o + 2) = h1;
            *reinterpret_cast<__nv_bfloat162*>(Al + o)     = l0;
            *reinterpret_cast<__nv_bfloat162*>(Al + o + 2) = l1;
            split4(pb[rep], h0, h1, l0, l1);
            o = (bn + rep * 32) * BPAD + bkc * 4;
            *reinterpret_cast<__nv_bfloat162*>(Bh + o)     = h0;
            *reinterpret_cast<__nv_bfloat162*>(Bh + o + 2) = h1;
            *reinterpret_cast<__nv_bfloat162*>(Bl + o)     = l0;
            *reinterpret_cast<__nv_bfloat162*>(Bl + o + 2) = l1;
        }
        __syncthreads();

        if (kc + 32 < EMB) {             // prefetch next K-tile; hides LDG under mma
            #pragma unroll
            for (int rep = 0; rep < 4; rep++) {
                pa[rep] = *reinterpret_cast<const float4*>(
                    xb + (size_t)(kc + 32 + ak + rep * 8) * SEQ + atc * 4);
                pb[rep] = *reinterpret_cast<const float4*>(
                    wgt + (size_t)(n0 + bn + rep * 32) * EMB + kc + 32 + bkc * 4);
            }
        }

        #pragma unroll
        for (int ks = 0; ks < 2; ks++) {
            wmma::fragment<wmma::matrix_a, 16, 16, 16, __nv_bfloat16, wmma::col_major> ah[4], al[4];
            wmma::fragment<wmma::matrix_b, 16, 16, 16, __nv_bfloat16, wmma::col_major> bh[2], bl[2];
            #pragma unroll
            for (int mf = 0; mf < 4; mf++) {
                const int o = ks * 16 * APAD + wm + mf * 16;
                wmma::load_matrix_sync(ah[mf], Ah + o, APAD);
                wmma::load_matrix_sync(al[mf], Al + o, APAD);
            }
            #pragma unroll
            for (int nf = 0; nf < 2; nf++) {
                const int o = (wn + nf * 16) * BPAD + ks * 16;
                wmma::load_matrix_sync(bh[nf], Bh + o, BPAD);
                wmma::load_matrix_sync(bl[nf], Bl + o, BPAD);
            }
            #pragma unroll
            for (int mf = 0; mf < 4; mf++)
                #pragma unroll
                for (int nf = 0; nf < 2; nf++) {
                    wmma::mma_sync(acc[mf][nf], ah[mf], bh[nf], acc[mf][nf]);
                    wmma::mma_sync(acc[mf][nf], ah[mf], bl[nf], acc[mf][nf]);
                    wmma::mma_sync(acc[mf][nf], al[mf], bh[nf], acc[mf][nf]);
                }
        }
    }
    __syncthreads();

    float* patch = reinterpret_cast<float*>(smem) + wrp * 256;
    const int pr = lane >> 1;
    const int pc = (lane & 1) * 8;
    #pragma unroll
    for (int mf = 0; mf < 4; mf++) {
        #pragma unroll
        for (int nf = 0; nf < 2; nf++) {
            wmma::store_matrix_sync(patch, acc[mf][nf], 16, wmma::mem_row_major);
            __syncwarp();
            const int gm = m0 + wm + mf * 16 + pr;
            const int gn = n0 + wn + nf * 16 + pc;
            float* dst = g_qkv + (size_t)gm * N3E + gn;
            #pragma unroll
            for (int j = 0; j < 8; j++)
                dst[j] = patch[pr * 16 + pc + j] + bias[gn + j];
            __syncwarp();
        }
    }
}

// ---------------------------------------------------------------------------
// GEMM2 (wmma bf16x3, fused split + transpose + relu(v*x)):
//   out[b,n,t] = relu((sum_k ctx[m,k]*Wo[n,k] + bo[n]) * x[b,n,t]),  m=b*SEQ+t
// ---------------------------------------------------------------------------
__global__ __launch_bounds__(256) void out_gemm_kernel(
    const float* __restrict__ x, const float* __restrict__ wgt,
    const float* __restrict__ bias, float* __restrict__ out)
{
    extern __shared__ __align__(128) __nv_bfloat16 smem[];
    __nv_bfloat16* Ah = smem;                 // [128][BPAD] (m, k) row-major A
    __nv_bfloat16* Al = Ah + B_TILE;
    __nv_bfloat16* Bh = Al + B_TILE;          // [128][BPAD] (n, k) row-major B
    __nv_bfloat16* Bl = Bh + B_TILE;

    const int tid  = threadIdx.x;
    const int wrp  = tid >> 5, lane = tid & 31;
    const int wm   = (wrp & 1) * 64;
    const int wn   = (wrp >> 1) * 32;
    const int m0   = blockIdx.y * 128;
    const int n0   = blockIdx.x * 128;
    const int b    = m0 / SEQ;
    const int t0   = m0 % SEQ;

    const int rn  = tid >> 3;            // +32 per rep (row within 128)
    const int rkc = tid & 7;

    wmma::fragment<wmma::accumulator, 16, 16, 16, float> acc[4][2];
    #pragma unroll
    for (int mf = 0; mf < 4; mf++)
        #pragma unroll
        for (int nf = 0; nf < 2; nf++)
            wmma::fill_fragment(acc[mf][nf], 0.0f);

    float4 pa[4], pb[4];
    #pragma unroll
    for (int rep = 0; rep < 4; rep++) {
        pa[rep] = *reinterpret_cast<const float4*>(
            g_ctx + (size_t)(m0 + rn + rep * 32) * EMB + rkc * 4);
        pb[rep] = *reinterpret_cast<const float4*>(
            wgt + (size_t)(n0 + rn + rep * 32) * EMB + rkc * 4);
    }

    for (int kc = 0; kc < EMB; kc += 32) {
        __syncthreads();
        #pragma unroll
        for (int rep = 0; rep < 4; rep++) {
            __nv_bfloat162 h0, h1, l0, l1;
            int o = (rn + rep * 32) * BPAD + rkc * 4;
            split4(pa[rep], h0, h1, l0, l1);
            *reinterpret_cast<__nv_bfloat162*>(Ah + o)     = h0;
            *reinterpret_cast<__nv_bfloat162*>(Ah + o + 2) = h1;
            *reinterpret_cast<__nv_bfloat162*>(Al + o)     = l0;
            *reinterpret_cast<__nv_bfloat162*>(Al + o + 2) = l1;
            split4(pb[rep], h0, h1, l0, l1);
            *reinterpret_cast<__nv_bfloat162*>(Bh + o)     = h0;
            *reinterpret_cast<__nv_bfloat162*>(Bh + o + 2) = h1;
            *reinterpret_cast<__nv_bfloat162*>(Bl + o)     = l0;
            *reinterpret_cast<__nv_bfloat162*>(Bl + o + 2) = l1;
        }
        __syncthreads();

        if (kc + 32 < EMB) {
            #pragma unroll
            for (int rep = 0; rep < 4; rep++) {
                pa[rep] = *reinterpret_cast<const float4*>(
                    g_ctx + (size_t)(m0 + rn + rep * 32) * EMB + kc + 32 + rkc * 4);
                pb[rep] = *reinterpret_cast<const float4*>(
                    wgt + (size_t)(n0 + rn + rep * 32) * EMB + kc + 32 + rkc * 4);
            }
        }

        #pragma unroll
        for (int ks = 0; ks < 2; ks++) {
            wmma::fragment<wmma::matrix_a, 16, 16, 16, __nv_bfloat16, wmma::row_major> ah[4], al[4];
            wmma::fragment<wmma::matrix_b, 16, 16, 16, __nv_bfloat16, wmma::col_major> bh[2], bl[2];
            #pragma unroll
            for (int mf = 0; mf < 4; mf++) {
                const int o = (wm + mf * 16) * BPAD + ks * 16;
                wmma::load_matrix_sync(ah[mf], Ah + o, BPAD);
                wmma::load_matrix_sync(al[mf], Al + o, BPAD);
            }
            #pragma unroll
            for (int nf = 0; nf < 2; nf++) {
                const int o = (wn + nf * 16) * BPAD + ks * 16;
                wmma::load_matrix_sync(bh[nf], Bh + o, BPAD);
                wmma::load_matrix_sync(bl[nf], Bl + o, BPAD);
            }
            #pragma unroll
            for (int mf = 0; mf < 4; mf++)
                #pragma unroll
                for (int nf = 0; nf < 2; nf++) {
                    wmma::mma_sync(acc[mf][nf], ah[mf], bh[nf], acc[mf][nf]);
                    wmma::mma_sync(acc[mf][nf], ah[mf], bl[nf], acc[mf][nf]);
                    wmma::mma_sync(acc[mf][nf], al[mf], bh[nf], acc[mf][nf]);
                }
        }
    }
    __syncthreads();

    // Epilogue: per-warp patch, transposed coalesced writes of relu(v * x).
    float* patch = reinterpret_cast<float*>(smem) + wrp * 256;
    const int pn = lane >> 1;            // local n 0..15
    const int pt = (lane & 1) * 8;       // 8 consecutive t per lane
    #pragma unroll
    for (int mf = 0; mf < 4; mf++) {
        #pragma unroll
        for (int nf = 0; nf < 2; nf++) {
            wmma::store_matrix_sync(patch, acc[mf][nf], 16, wmma::mem_row_major);
            __syncwarp();
            const int gn = n0 + wn + nf * 16 + pn;
            const int gt = t0 + wm + mf * 16 + pt;
            const float bb = bias[gn];
            const size_t base = (size_t)b * EMB * SEQ + (size_t)gn * SEQ + gt;
            #pragma unroll
            for (int j = 0; j < 8; j++) {
                const float v = patch[(pt + j) * 16 + pn] + bb;
                const float r = v * x[base + j];
                out[base + j] = r > 0.f ? r : 0.f;
            }
            __syncwarp();
        }
    }
}

// ---------------- local-window attention (known-good, fp32 ctx out) ----------------
__global__ __launch_bounds__(256) void attn_kernel()
{
    extern __shared__ float sm[];
    float* Qs = sm;               // 64 * 64
    float* Ks = Qs + 64 * 64;     // 192 * 65
    float* Vs = Ks + 192 * 65;    // 192 * 64

    const int b  = blockIdx.z;
    const int h  = blockIdx.y;
    const int q0 = blockIdx.x * 64;
    const int tid = threadIdx.x;
    const float* base = g_qkv + (size_t)b * SEQ * N3E;
    const int qoff = h * DHEAD;
    const int koff = EMB + h * DHEAD;
    const int voff = 2 * EMB + h * DHEAD;

    for (int i = tid; i < 64 * 64; i += 256) {
        int qi = i >> 6, d = i & 63;
        Qs[qi * 64 + d] = base[(size_t)(q0 + qi) * N3E + qoff + d];
    }
    const int kstart = q0 - HWIN;
    for (int i = tid; i < 192 * 64; i += 256) {
        int ki = i >> 6, d = i & 63;
        int t = kstart + ki;
        float kv = 0.f, vv = 0.f;
        if (t >= 0 && t < SEQ) {
            kv = base[(size_t)t * N3E + koff + d];
            vv = base[(size_t)t * N3E + voff + d];
        }
        Ks[ki * 65 + d] = kv;
        Vs[ki * 64 + d] = vv;
    }
    __syncthreads();

    const int warp = tid >> 5, lane = tid & 31;
    const int qbase = warp * 8;
    const float scale = 0.125f;

    float s[8][6];
    #pragma unroll
    for (int u = 0; u < 8; u++)
        #pragma unroll
        for (int kk = 0; kk < 6; kk++) s[u][kk] = 0.f;

    for (int d = 0; d < 64; d++) {
        float kv[6];
        #pragma unroll
        for (int kk = 0; kk < 6; kk++) kv[kk] = Ks[(lane + kk * 32) * 65 + d];
        #pragma unroll
        for (int u = 0; u < 8; u++) {
            float qv = Qs[(qbase + u) * 64 + d];
            #pragma unroll
            for (int kk = 0; kk < 6; kk++) s[u][kk] += qv * kv[kk];
        }
    }

    #pragma unroll
    for (int u = 0; u < 8; u++) {
        int qi = qbase + u;
        float mx = -1e30f;
        #pragma unroll
        for (int kk = 0; kk < 6; kk++) {
            int ki = lane + kk * 32;
            int t = kstart + ki;
            bool valid = (t >= 0) && (t < SEQ) && (ki >= qi) && (ki <= qi + 128);
            s[u][kk] = valid ? s[u][kk] * scale : -1e30f;
            mx = fmaxf(mx, s[u][kk]);
        }
        #pragma unroll
        for (int off = 16; off; off >>= 1)
            mx = fmaxf(mx, __shfl_xor_sync(0xffffffffu, mx, off));
        float sum = 0.f;
        #pragma unroll
        for (int kk = 0; kk < 6; kk++) { s[u][kk] = __expf(s[u][kk] - mx); sum += s[u][kk]; }
        #pragma unroll
        for (int off = 16; off; off >>= 1)
            sum += __shfl_xor_sync(0xffffffffu, sum, off);
        float inv = 1.f / sum;
        #pragma unroll
        for (int kk = 0; kk < 6; kk++) s[u][kk] *= inv;
    }

    float a0[8], a1[8];
    #pragma unroll
    for (int u = 0; u < 8; u++) { a0[u] = 0.f; a1[u] = 0.f; }

    #pragma unroll
    for (int kk = 0; kk < 6; kk++) {
        #pragma unroll 8
        for (int src = 0; src < 32; src++) {
            int ki = kk * 32 + src;
            float2 v = *reinterpret_cast<const float2*>(&Vs[ki * 64 + 2 * lane]);
            #pragma unroll
            for (int u = 0; u < 8; u++) {
                float p = __shfl_sync(0xffffffffu, s[u][kk], src);
                a0[u] += p * v.x;
                a1[u] += p * v.y;
            }
        }
    }

    #pragma unroll
    for (int u = 0; u < 8; u++) {
        int q = q0 + qbase + u;
        float2* dst = reinterpret_cast<float2*>(
            g_ctx + ((size_t)(b * SEQ + q)) * EMB + qoff + 2 * lane);
        *dst = make_float2(a0[u], a1[u]);
    }
}

// ---------------------------------------------------------------------------
extern "C" void kernel_launch(void* const* d_in, const int* in_sizes, int n_in,
                              void* d_out, int out_size)
{
    const float* x  = (const float*)d_in[0];   // [B, E, T]
    const float* wi = (const float*)d_in[1];   // [3E, E]
    const float* bi = (const float*)d_in[2];   // [3E]
    const float* wo = (const float*)d_in[3];   // [E, E]
    const float* bo = (const float*)d_in[4];   // [E]
    float* out = (float*)d_out;                // [B, E, T]

    const int gemm1_smem = (2 * A_TILE + 2 * B_TILE) * (int)sizeof(__nv_bfloat16) + 128;
    const int gemm2_smem = (4 * B_TILE) * (int)sizeof(__nv_bfloat16) + 128;
    const int attn_smem  = (64 * 64 + 192 * 65 + 192 * 64) * (int)sizeof(float);

    cudaFuncSetAttribute(qkv_gemm_kernel,
                         cudaFuncAttributeMaxDynamicSharedMemorySize, gemm1_smem);
    cudaFuncSetAttribute(out_gemm_kernel,
                         cudaFuncAttributeMaxDynamicSharedMemorySize, gemm2_smem);
    cudaFuncSetAttribute(attn_kernel,
                         cudaFuncAttributeMaxDynamicSharedMemorySize, attn_smem);

    qkv_gemm_kernel<<<dim3(N3E / 128, MTOT / 128), 256, gemm1_smem>>>(x, wi, bi);
    attn_kernel<<<dim3(SEQ / 64, NH, BATCH), 256, attn_smem>>>();
    out_gemm_kernel<<<dim3(EMB / 128, MTOT / 128), 256, gemm2_smem>>>(x, wo, bo, out);
}